// round 1
// baseline (speedup 1.0000x reference)
#include <cuda_runtime.h>
#include <cuda_bf16.h>
#include <math_constants.h>

// Problem constants
#define T_TOKENS 4096
#define HIDDEN   2048
#define N_EXP    8
#define H4       (HIDDEN / 4)          // 512 float4 per row

// Output layout (floats), outputs concatenated:
//   [0, 32768)                      router_scores [E, T]
//   [32768, 32768+67108864)         router_indices [E*T, H]  (value = t, as float)
//   [67141632, 67174400)            router_probs [E*T, 1] == scores flattened
#define SCORES_OFF 0
#define IDX_OFF    (N_EXP * T_TOKENS)                       // 32768
#define IDX_ELEMS  ((size_t)N_EXP * T_TOKENS * HIDDEN)      // 67108864
#define PROBS_OFF  (IDX_OFF + IDX_ELEMS)                    // 67141632

// ---------------------------------------------------------------------------
// Kernel A: router logits + top-2 + sigmoid scatter.
// 8 warps/block, 4 tokens/warp -> 32 tokens/block, 128 blocks.
// Each lane strides hidden dim in float4; w float4 loads are amortized over
// 4 tokens (w is 64 KB, stays L1/L2 resident).
// ---------------------------------------------------------------------------
__global__ __launch_bounds__(256, 4)
void router_logits_kernel(const float* __restrict__ hs,
                          const float* __restrict__ wr,
                          float* __restrict__ out) {
    const int warp = threadIdx.x >> 5;
    const int lane = threadIdx.x & 31;
    const int TPW = 4;                       // tokens per warp
    const int t0 = blockIdx.x * (8 * TPW) + warp * TPW;

    const float4* __restrict__ hs4 = (const float4*)hs;
    const float4* __restrict__ w4  = (const float4*)wr;

    float acc[TPW][N_EXP];
#pragma unroll
    for (int a = 0; a < TPW; a++)
#pragma unroll
        for (int e = 0; e < N_EXP; e++) acc[a][e] = 0.f;

    for (int i = lane; i < H4; i += 32) {
        float4 wv[N_EXP];
#pragma unroll
        for (int e = 0; e < N_EXP; e++) wv[e] = w4[e * H4 + i];
#pragma unroll
        for (int a = 0; a < TPW; a++) {
            float4 x = hs4[(size_t)(t0 + a) * H4 + i];
#pragma unroll
            for (int e = 0; e < N_EXP; e++) {
                acc[a][e] += x.x * wv[e].x + x.y * wv[e].y
                           + x.z * wv[e].z + x.w * wv[e].w;
            }
        }
    }

    // butterfly warp reduction: every lane ends with full sums
#pragma unroll
    for (int a = 0; a < TPW; a++)
#pragma unroll
        for (int e = 0; e < N_EXP; e++)
#pragma unroll
            for (int o = 16; o > 0; o >>= 1)
                acc[a][e] += __shfl_xor_sync(0xffffffffu, acc[a][e], o);

    if (lane == 0) {
#pragma unroll
        for (int a = 0; a < TPW; a++) {
            const int t = t0 + a;
            // top-1
            float b1 = -CUDART_INF_F; int i1 = 0;
#pragma unroll
            for (int e = 0; e < N_EXP; e++)
                if (acc[a][e] > b1) { b1 = acc[a][e]; i1 = e; }
            // top-2 (excluding i1)
            float b2 = -CUDART_INF_F; int i2 = -1;
#pragma unroll
            for (int e = 0; e < N_EXP; e++)
                if (e != i1 && acc[a][e] > b2) { b2 = acc[a][e]; i2 = e; }

            const float s1 = 1.f / (1.f + __expf(-b1));
            const float s2 = 1.f / (1.f + __expf(-b2));
#pragma unroll
            for (int e = 0; e < N_EXP; e++) {
                float s = (e == i1) ? s1 : ((e == i2) ? s2 : 0.f);
                out[SCORES_OFF + (size_t)e * T_TOKENS + t] = s;
                out[PROBS_OFF  + (size_t)e * T_TOKENS + t] = s;
            }
        }
    }
}

// ---------------------------------------------------------------------------
// Kernel B: fill the router_indices region. Pure pattern write, 256 MB.
// Each float4 j covers 4 floats of row (e*T + t); t = (j >> 9) & 4095
// since H/4 = 512 float4 per row and rows cycle over T = 4096 tokens.
// ---------------------------------------------------------------------------
__global__ __launch_bounds__(256)
void fill_indices_kernel(float4* __restrict__ out4) {
    const size_t i = (size_t)blockIdx.x * blockDim.x + threadIdx.x;
    const float v = (float)((i >> 9) & (T_TOKENS - 1));
    out4[i] = make_float4(v, v, v, v);
}

extern "C" void kernel_launch(void* const* d_in, const int* in_sizes, int n_in,
                              void* d_out, int out_size) {
    const float* hs = (const float*)d_in[0];  // [T, H] fp32
    const float* wr = (const float*)d_in[1];  // [E, H] fp32
    float* out = (float*)d_out;

    // Kernel A: 128 blocks x 256 threads (32 tokens per block)
    router_logits_kernel<<<T_TOKENS / 32, 256>>>(hs, wr, out);

    // Kernel B: 16,777,216 float4 stores
    const size_t n4 = IDX_ELEMS / 4;          // 16777216
    fill_indices_kernel<<<(unsigned)(n4 / 256), 256>>>((float4*)(out + IDX_OFF));
}

// round 2
// speedup vs baseline: 1.5456x; 1.5456x over previous
#include <cuda_runtime.h>
#include <cuda_bf16.h>
#include <math_constants.h>

// Problem constants
#define T_TOKENS 4096
#define HIDDEN   2048
#define N_EXP    8
#define H4       (HIDDEN / 4)          // 512 float4 per hidden row

// Output layout (floats), outputs concatenated:
//   [0, 32768)                router_scores [E, T]
//   [32768, +67108864)        router_indices [E*T, H] (value = t, as float)
//   [67141632, 67174400)      router_probs [E*T, 1] == scores flattened
#define SCORES_OFF 0
#define IDX_OFF    (N_EXP * T_TOKENS)                       // 32768
#define IDX_ELEMS  ((size_t)N_EXP * T_TOKENS * HIDDEN)      // 67108864
#define PROBS_OFF  (IDX_OFF + IDX_ELEMS)                    // 67141632

// Grid partition: logits blocks first (reads overlap the fill writes)
#define LOGITS_BLOCKS 512                 // 8 tokens/block (1 token per warp)
#define FILL_F4_PER_BLOCK 1024            // 4 float4 per thread, 256 threads
#define FILL_BLOCKS (16777216 / FILL_F4_PER_BLOCK)   // 16384
#define SMEM_BYTES (N_EXP * HIDDEN * 4)   // 64 KB for w_router

__global__ __launch_bounds__(256, 3)
void router_fused_kernel(const float* __restrict__ hs,
                         const float* __restrict__ wr,
                         float* __restrict__ out) {
    // ---------------- fill branch (blocks >= LOGITS_BLOCKS) ----------------
    if (blockIdx.x >= LOGITS_BLOCKS) {
        const size_t bid = blockIdx.x - LOGITS_BLOCKS;
        float4* __restrict__ out4 = (float4*)(out + IDX_OFF);
        const size_t base = bid * FILL_F4_PER_BLOCK + threadIdx.x;
#pragma unroll
        for (int j = 0; j < 4; j++) {
            const size_t i = base + (size_t)j * 256;
            const float v = (float)((i >> 9) & (T_TOKENS - 1));
            __stcs(&out4[i], make_float4(v, v, v, v));
        }
        return;
    }

    // ---------------- logits branch (blocks < LOGITS_BLOCKS) ----------------
    extern __shared__ float wsm[];                 // [E * H] = 64 KB
    const float4* __restrict__ w4 = (const float4*)wr;
    float4* __restrict__ ws4 = (float4*)wsm;
    for (int i = threadIdx.x; i < N_EXP * H4; i += 256)
        ws4[i] = w4[i];
    __syncthreads();

    const int warp = threadIdx.x >> 5;
    const int lane = threadIdx.x & 31;
    const int t = blockIdx.x * 8 + warp;           // one token per warp

    const float4* __restrict__ hs4 = (const float4*)hs + (size_t)t * H4;

    float acc[N_EXP];
#pragma unroll
    for (int e = 0; e < N_EXP; e++) acc[e] = 0.f;

#pragma unroll
    for (int ii = 0; ii < H4 / 32; ii++) {         // 16 iterations
        const int i = ii * 32 + lane;
        const float4 x = hs4[i];
#pragma unroll
        for (int e = 0; e < N_EXP; e++) {
            const float4 wv = ws4[e * H4 + i];
            acc[e] += x.x * wv.x + x.y * wv.y + x.z * wv.z + x.w * wv.w;
        }
    }

    // butterfly warp reduction: every lane ends with full sums
#pragma unroll
    for (int e = 0; e < N_EXP; e++)
#pragma unroll
        for (int o = 16; o > 0; o >>= 1)
            acc[e] += __shfl_xor_sync(0xffffffffu, acc[e], o);

    if (lane == 0) {
        // top-1
        float b1 = -CUDART_INF_F; int i1 = 0;
#pragma unroll
        for (int e = 0; e < N_EXP; e++)
            if (acc[e] > b1) { b1 = acc[e]; i1 = e; }
        // top-2 (excluding i1)
        float b2 = -CUDART_INF_F; int i2 = -1;
#pragma unroll
        for (int e = 0; e < N_EXP; e++)
            if (e != i1 && acc[e] > b2) { b2 = acc[e]; i2 = e; }

        const float s1 = 1.f / (1.f + __expf(-b1));
        const float s2 = 1.f / (1.f + __expf(-b2));
#pragma unroll
        for (int e = 0; e < N_EXP; e++) {
            const float s = (e == i1) ? s1 : ((e == i2) ? s2 : 0.f);
            out[SCORES_OFF + (size_t)e * T_TOKENS + t] = s;
            out[PROBS_OFF  + (size_t)e * T_TOKENS + t] = s;
        }
    }
}

extern "C" void kernel_launch(void* const* d_in, const int* in_sizes, int n_in,
                              void* d_out, int out_size) {
    const float* hs = (const float*)d_in[0];  // [T, H] fp32
    const float* wr = (const float*)d_in[1];  // [E, H] fp32
    float* out = (float*)d_out;

    static int attr_set = 0;
    // Idempotent host-side attribute set (same every call; not a work guard).
    cudaFuncSetAttribute(router_fused_kernel,
                         cudaFuncAttributeMaxDynamicSharedMemorySize, SMEM_BYTES);
    (void)attr_set;

    router_fused_kernel<<<LOGITS_BLOCKS + FILL_BLOCKS, 256, SMEM_BYTES>>>(hs, wr, out);
}